// round 8
// baseline (speedup 1.0000x reference)
#include <cuda_runtime.h>
#include <cstdint>

#define N_MAX 100000
#define E_MAX 600000
#define HF 128

// ---------------- scratch (static __device__ — no allocation) ----------------
__device__ __align__(16) float d_bufA[N_MAX * HF];
__device__ __align__(16) float d_bufB[N_MAX * HF];
__device__ int   d_cnt[N_MAX];
__device__ int   d_incl[N_MAX];
__device__ int   d_rs[N_MAX + 1];
__device__ int   d_cursor[N_MAX];
__device__ int   d_csr[E_MAX];
__device__ float d_dinv[N_MAX];
__device__ float d_sc[N_MAX];     // dinv/deg
__device__ int   d_bsum[256];
__device__ int   d_bpref[256];

// ---------------- preprocessing: CSR-by-target + degree terms ----------------
__global__ void k_hist(const int* __restrict__ col, int e, int n) {
    int i = blockIdx.x * blockDim.x + threadIdx.x;
    if (i < e) {
        int c = col[i];
        if (c >= 0 && c < n) atomicAdd(&d_cnt[c], 1);
    }
}

__global__ void k_scan1(int n) {
    __shared__ int s[1024];
    int t = threadIdx.x;
    int i = blockIdx.x * 1024 + t;
    s[t] = (i < n) ? d_cnt[i] : 0;
    __syncthreads();
    for (int off = 1; off < 1024; off <<= 1) {
        int a = 0;
        if (t >= off) a = s[t - off];
        __syncthreads();
        s[t] += a;
        __syncthreads();
    }
    if (i < n) d_incl[i] = s[t];
    if (t == 1023) d_bsum[blockIdx.x] = s[1023];
}

__global__ void k_scan2(int nb) {   // single warp, shfl scan with carry
    int lane = threadIdx.x;
    int carry = 0;
    for (int base = 0; base < nb; base += 32) {
        int i = base + lane;
        int own = (i < nb) ? d_bsum[i] : 0;
        int v = own;
        #pragma unroll
        for (int o = 1; o < 32; o <<= 1) {
            int t = __shfl_up_sync(0xffffffffu, v, o);
            if (lane >= o) v += t;
        }
        if (i < nb) d_bpref[i] = carry + v - own;   // exclusive
        carry += __shfl_sync(0xffffffffu, v, 31);
    }
}

__global__ void k_scan3(int n) {
    int i = blockIdx.x * blockDim.x + threadIdx.x;
    if (i >= n) return;
    int gi = d_incl[i] + d_bpref[i >> 10];
    int c  = d_cnt[i];
    d_cnt[i] = 0;                        // re-zero for next graph replay
    int st = gi - c;
    d_rs[i] = st;
    d_cursor[i] = st;
    if (i == n - 1) d_rs[n] = gi;
    float deg = (float)(c + 1);          // degree incl. self-loop
    float di = rsqrtf(deg);
    d_dinv[i] = di;
    d_sc[i]   = di / deg;
}

__global__ void k_scatter(const int* __restrict__ ei, int e, int n) {
    int i = blockIdx.x * blockDim.x + threadIdx.x;
    if (i >= e) return;
    int c = ei[e + i];  // col (target)
    int r = ei[i];      // row (source)
    if (c < 0 || c >= n || r < 0 || r >= n) return;
    int pos = atomicAdd(&d_cursor[c], 1);
    d_csr[pos] = r;
}

// ---------------- fused (aggregate +) GEMM ----------------
// dst = rowscale * (Agg(src) @ W^T + bias), optional epilogue relu.
// gather=0: A row = src row (optionally * colscale)           [conv1 / plain]
// gather=1: A row = relu(sc[r]*(src[r]+sum_csr src[j]) + aggbias)  [conv aggregation]
// 128x128 tile, 256 threads, 8x8 microtile, K in 4 chunks of 32, single-stage A.
// smem: Bs[128][128] XOR-swizzled @0 (64KB); As[128][36] @65536 (18KB). 2 CTAs/SM.
#define OFF_AS  65536
#define APITCH  36
#define GEMM_SMEM (OFF_AS + 128 * APITCH * 4)   // 83968

__device__ __forceinline__ void add4(float4& a, float4 b) {
    a.x += b.x; a.y += b.y; a.z += b.z; a.w += b.w;
}

__global__ void __launch_bounds__(256, 2) k_gemm_f(
    const float* __restrict__ xext,       // external A (srcsel==0)
    const float* __restrict__ W,
    const float* __restrict__ bias,       // GEMM bias [128]
    const float* __restrict__ colscale,   // nullptr or [128] (simple mode)
    const float* __restrict__ aggbias,    // conv bias bc [128] (gather mode)
    int srcsel,                           // 0=xext, 1=bufA, 2=bufB
    int dstsel,                           // 1=bufA, 2=bufB
    int gather, int use_dinv, int relu, int n)
{
    extern __shared__ __align__(16) char sm[];
    float* Bs = (float*)sm;
    float* As = (float*)(sm + OFF_AS);
    int tid = threadIdx.x;
    int tx = tid & 15, ty = tid >> 4;
    int row0 = blockIdx.x * 128;

    const float* S = (srcsel == 0) ? xext : (srcsel == 1 ? d_bufA : d_bufB);
    float* D = (dstsel == 1) ? d_bufA : d_bufB;
    const float4* S4 = (const float4*)S;

    // ---- load full W transposed with XOR swizzle: Bs[k][j ^ (k&31)] = W[j][k] ----
    {
        const float4* W4 = (const float4*)W;
        #pragma unroll
        for (int it = 0; it < 16; ++it) {
            int idx = tid + it * 256;           // 0..4095
            int j = idx >> 5, kq = idx & 31;
            float4 v = W4[j * 32 + kq];
            int k0 = kq * 4;
            Bs[(k0 + 0) * 128 + (j ^ ((k0 + 0) & 31))] = v.x;
            Bs[(k0 + 1) * 128 + (j ^ ((k0 + 1) & 31))] = v.y;
            Bs[(k0 + 2) * 128 + (j ^ ((k0 + 2) & 31))] = v.z;
            Bs[(k0 + 3) * 128 + (j ^ ((k0 + 3) & 31))] = v.w;
        }
    }

    float acc[8][8];
    #pragma unroll
    for (int i = 0; i < 8; i++)
        #pragma unroll
        for (int j = 0; j < 8; j++) acc[i][j] = 0.f;

    // thread's loader assignment: row r, 16-col half h of each 32-col chunk
    int lr = tid >> 1, lh = tid & 1;
    int lgr = row0 + lr;

    for (int kc = 0; kc < 4; ++kc) {
        // ---- build A chunk [128 rows x 32 cols] ----
        {
            float4 a0 = make_float4(0.f, 0.f, 0.f, 0.f);
            float4 a1 = a0, a2 = a0, a3 = a0;
            if (lgr < n) {
                size_t base = (size_t)lgr * 32 + kc * 8 + lh * 4;
                a0 = S4[base + 0];
                a1 = S4[base + 1];
                a2 = S4[base + 2];
                a3 = S4[base + 3];
                if (gather) {
                    int beg = d_rs[lgr], end = d_rs[lgr + 1];
                    for (int e2 = beg; e2 < end; ++e2) {
                        int s = d_csr[e2];
                        size_t b2 = (size_t)s * 32 + kc * 8 + lh * 4;
                        add4(a0, S4[b2 + 0]);
                        add4(a1, S4[b2 + 1]);
                        add4(a2, S4[b2 + 2]);
                        add4(a3, S4[b2 + 3]);
                    }
                    float kf = d_sc[lgr];
                    int c0 = kc * 32 + lh * 16;
                    const float4* bc4 = (const float4*)(aggbias + c0);
                    float4 b;
                    b = bc4[0];
                    a0.x = fmaxf(kf * a0.x + b.x, 0.f); a0.y = fmaxf(kf * a0.y + b.y, 0.f);
                    a0.z = fmaxf(kf * a0.z + b.z, 0.f); a0.w = fmaxf(kf * a0.w + b.w, 0.f);
                    b = bc4[1];
                    a1.x = fmaxf(kf * a1.x + b.x, 0.f); a1.y = fmaxf(kf * a1.y + b.y, 0.f);
                    a1.z = fmaxf(kf * a1.z + b.z, 0.f); a1.w = fmaxf(kf * a1.w + b.w, 0.f);
                    b = bc4[2];
                    a2.x = fmaxf(kf * a2.x + b.x, 0.f); a2.y = fmaxf(kf * a2.y + b.y, 0.f);
                    a2.z = fmaxf(kf * a2.z + b.z, 0.f); a2.w = fmaxf(kf * a2.w + b.w, 0.f);
                    b = bc4[3];
                    a3.x = fmaxf(kf * a3.x + b.x, 0.f); a3.y = fmaxf(kf * a3.y + b.y, 0.f);
                    a3.z = fmaxf(kf * a3.z + b.z, 0.f); a3.w = fmaxf(kf * a3.w + b.w, 0.f);
                } else if (colscale) {
                    int c0 = kc * 32 + lh * 16;
                    const float4* cs4 = (const float4*)(colscale + c0);
                    float4 c;
                    c = cs4[0]; a0.x *= c.x; a0.y *= c.y; a0.z *= c.z; a0.w *= c.w;
                    c = cs4[1]; a1.x *= c.x; a1.y *= c.y; a1.z *= c.z; a1.w *= c.w;
                    c = cs4[2]; a2.x *= c.x; a2.y *= c.y; a2.z *= c.z; a2.w *= c.w;
                    c = cs4[3]; a3.x *= c.x; a3.y *= c.y; a3.z *= c.z; a3.w *= c.w;
                }
            }
            float* dst = As + lr * APITCH + lh * 16;
            *(float4*)(dst + 0)  = a0;
            *(float4*)(dst + 4)  = a1;
            *(float4*)(dst + 8)  = a2;
            *(float4*)(dst + 12) = a3;
        }
        __syncthreads();

        // ---- compute 32 k-steps ----
        #pragma unroll 4
        for (int kl = 0; kl < 32; ++kl) {
            int k = kc * 32 + kl;
            int f = k & 31;
            float a[8], b[8];
            #pragma unroll
            for (int ii = 0; ii < 8; ii++) a[ii] = As[(ty + ii * 16) * APITCH + kl];
            #pragma unroll
            for (int jj = 0; jj < 8; jj++) b[jj] = Bs[k * 128 + ((tx + jj * 16) ^ f)];
            #pragma unroll
            for (int ii = 0; ii < 8; ii++)
                #pragma unroll
                for (int jj = 0; jj < 8; jj++)
                    acc[ii][jj] += a[ii] * b[jj];
        }
        __syncthreads();
    }

    // ---- epilogue: bias, rowscale, optional relu ----
    #pragma unroll
    for (int ii = 0; ii < 8; ii++) {
        int gr = row0 + ty + ii * 16;
        if (gr >= n) continue;
        float rs = use_dinv ? d_dinv[gr] : 1.f;
        #pragma unroll
        for (int jj = 0; jj < 8; jj++) {
            int jc = tx + jj * 16;
            float v = (acc[ii][jj] + bias[jc]) * rs;
            if (relu) v = fmaxf(v, 0.f);
            D[(size_t)gr * 128 + jc] = v;
        }
    }
}

// ---------------- final linear (H=128 -> C=40) + log_softmax, one THREAD per row ----------
// smem: rowt[128][132] @0 (67584B), Ws2[128][40] k-major @67584 (20480B). 2 CTAs/SM.
#define L2_ROWT  0
#define L2_WS    67584
#define L2_SMEM  88064

__global__ void __launch_bounds__(128, 2) k_lin2(
    const float* __restrict__ W2, const float* __restrict__ b2,
    float* __restrict__ out, int n)
{
    extern __shared__ __align__(16) char sm[];
    float* rowt = (float*)(sm + L2_ROWT);    // pitch 132
    float* Ws2  = (float*)(sm + L2_WS);      // Ws2[k*40 + c] = W2[c*128 + k]
    int tid = threadIdx.x;
    int row0 = blockIdx.x * 128;

    // load W2 transposed (k-major for broadcast)
    for (int idx = tid; idx < 40 * 128; idx += 128) {
        int c = idx >> 7, k = idx & 127;
        Ws2[k * 40 + c] = W2[idx];
    }
    // load 128-row tile coalesced
    {
        const float4* h4 = (const float4*)d_bufB;
        #pragma unroll
        for (int it = 0; it < 32; ++it) {
            int idx = tid + it * 128;            // 0..4095
            int r = idx >> 5, c4 = idx & 31;
            float4 v = make_float4(0.f, 0.f, 0.f, 0.f);
            int gr = row0 + r;
            if (gr < n) v = h4[(size_t)gr * 32 + c4];
            *(float4*)(rowt + r * 132 + c4 * 4) = v;
        }
    }
    __syncthreads();

    int row = row0 + tid;
    if (row >= n) return;

    float acc[40];
    #pragma unroll
    for (int c = 0; c < 40; ++c) acc[c] = b2[c];

    const float* myrow = rowt + tid * 132;
    #pragma unroll 4
    for (int k = 0; k < 128; ++k) {
        float a = myrow[k];
        const float* wk = Ws2 + k * 40;
        #pragma unroll
        for (int c = 0; c < 40; ++c) acc[c] += a * wk[c];
    }

    // log_softmax over the 40 register values
    float m = acc[0];
    #pragma unroll
    for (int c = 1; c < 40; ++c) m = fmaxf(m, acc[c]);
    float ssum = 0.f;
    #pragma unroll
    for (int c = 0; c < 40; ++c) ssum += __expf(acc[c] - m);
    float ls = m + __logf(ssum);

    float4* o4 = (float4*)(out + (size_t)row * 40);
    #pragma unroll
    for (int q = 0; q < 10; ++q) {
        float4 o;
        o.x = acc[q * 4 + 0] - ls;
        o.y = acc[q * 4 + 1] - ls;
        o.z = acc[q * 4 + 2] - ls;
        o.w = acc[q * 4 + 3] - ls;
        o4[q] = o;
    }
}

// ---------------- launch ----------------
extern "C" void kernel_launch(void* const* d_in, const int* in_sizes, int n_in,
                              void* d_out, int out_size)
{
    const float* x    = (const float*)d_in[0];
    const int*   ei   = (const int*)d_in[1];     // int32 (JAX x64 disabled)
    const float* imp  = (const float*)d_in[2];
    const float* W1   = (const float*)d_in[3];
    const float* bl1  = (const float*)d_in[4];
    const float* bc1  = (const float*)d_in[5];
    const float* W2   = (const float*)d_in[6];
    const float* bl2  = (const float*)d_in[7];
    const float* bc2  = (const float*)d_in[8];
    const float* W3   = (const float*)d_in[9];
    const float* bl3  = (const float*)d_in[10];
    const float* bc3  = (const float*)d_in[11];
    const float* Wl1  = (const float*)d_in[12];
    const float* bli1 = (const float*)d_in[13];
    const float* Wl2  = (const float*)d_in[14];
    const float* bli2 = (const float*)d_in[15];
    int n = in_sizes[0] / HF;
    int e = in_sizes[1] / 2;
    float* out = (float*)d_out;

    cudaFuncSetAttribute(k_gemm_f, cudaFuncAttributeMaxDynamicSharedMemorySize, GEMM_SMEM);
    cudaFuncSetAttribute(k_lin2, cudaFuncAttributeMaxDynamicSharedMemorySize, L2_SMEM);

    // preprocessing: CSR build + degree scaling
    k_hist   <<<(e + 255) / 256, 256>>>(ei + e, e, n);
    int nb = (n + 1023) / 1024;
    k_scan1  <<<nb, 1024>>>(n);
    k_scan2  <<<1, 32>>>(nb);
    k_scan3  <<<(n + 255) / 256, 256>>>(n);
    k_scatter<<<(e + 255) / 256, 256>>>(ei, e, n);

    int gblocks = (n + 127) / 128;

    // conv1 lin: A = x*imp (simple load), out = dinv*(A@W1^T+bl1) -> bufA
    k_gemm_f<<<gblocks, 256, GEMM_SMEM>>>(x, W1, bl1, imp, nullptr,
                                          0, 1, 0, 1, 0, n);
    // conv2: gather(bufA, bc1) -> GEMM W2 -> bufB
    k_gemm_f<<<gblocks, 256, GEMM_SMEM>>>(nullptr, W2, bl2, nullptr, bc1,
                                          1, 2, 1, 1, 0, n);
    // conv3: gather(bufB, bc2) -> GEMM W3 -> bufA
    k_gemm_f<<<gblocks, 256, GEMM_SMEM>>>(nullptr, W3, bl3, nullptr, bc2,
                                          2, 1, 1, 1, 0, n);
    // lin1: gather(bufA, bc3) [conv3 agg+relu] -> GEMM Wl1 + bli1, relu -> bufB
    k_gemm_f<<<gblocks, 256, GEMM_SMEM>>>(nullptr, Wl1, bli1, nullptr, bc3,
                                          1, 2, 1, 0, 1, n);
    // lin2 + log_softmax (reads bufB)
    k_lin2<<<gblocks, 128, L2_SMEM>>>(Wl2, bli2, out, n);
}